// round 6
// baseline (speedup 1.0000x reference)
#include <cuda_runtime.h>
#include <cuda_fp16.h>
#include <cstdint>

// RoIAlign1D: B=8, LV=4096, D=256, N=2048 boxes, P=32 bins.
// R5: issue-bound. (1) packed f32x2 FFMA via PTX (8 FFMA -> 4 FFMA2/row),
// (2) one block per BOX (256 thr): Phase A + prologue amortized over 32 bins,
// warp = full 256-ch row, 4 bins per warp processed sequentially, direct stores.

#define B_    8
#define LV_   4096
#define D_    256
#define N_    2048
#define P_    32
#define WINB_ 136   // per-bin row window: bin_h<=128 -> <=131 rows + slack

// 16 MB fp16 copy of feat (static device scratch; no allocation APIs used)
__device__ __half g_feat16[B_ * LV_ * D_];

// ---- pre-pass: f32 -> f16, 8 floats per thread, fully coalesced ----
__global__ __launch_bounds__(256) void cvt_kernel(const float* __restrict__ feat)
{
    const int i = blockIdx.x * 256 + threadIdx.x;       // uint4 (8-half) index
    const float4* src = reinterpret_cast<const float4*>(feat) + 2 * (size_t)i;
    float4 v0 = src[0];
    float4 v1 = src[1];
    __half2 h0 = __floats2half2_rn(v0.x, v0.y);
    __half2 h1 = __floats2half2_rn(v0.z, v0.w);
    __half2 h2 = __floats2half2_rn(v1.x, v1.y);
    __half2 h3 = __floats2half2_rn(v1.z, v1.w);
    uint4 o;
    o.x = *reinterpret_cast<unsigned int*>(&h0);
    o.y = *reinterpret_cast<unsigned int*>(&h1);
    o.z = *reinterpret_cast<unsigned int*>(&h2);
    o.w = *reinterpret_cast<unsigned int*>(&h3);
    reinterpret_cast<uint4*>(g_feat16)[i] = o;
}

__global__ __launch_bounds__(256, 6) void roi_align1d_kernel(
    const float* __restrict__ boxes,   // [N, 2]
    const int*   __restrict__ bidx,    // [N]
    float*       __restrict__ out)     // [N, P, D]
{
    __shared__ float w_s[P_][WINB_];   // per-bin bilinear row weights
    __shared__ int   rmin_s[P_], rmax_s[P_];

    const int n    = blockIdx.x;       // box
    const int tid  = threadIdx.x;      // 0..255
    const int wid  = tid >> 5;         // 0..7
    const int lane = tid & 31;

    // ---- box scalars (identical expressions used in Phase A and B) ----
    const float y1    = boxes[2 * n];
    const float y2    = boxes[2 * n + 1];
    const float roi_h = y2 - y1;
    const float bin_h = roi_h * (1.0f / (float)P_);   // exact: /32
    const int   grid_h = (int)ceilf(bin_h);
    const int   cnt    = max(grid_h, 1);
    const float sub    = bin_h / (float)cnt;
    const float start  = y1 - 0.5f;

    // ---- zero per-bin weight windows (4352 floats = 1088 float4) ----
    {
        float4* wz = reinterpret_cast<float4*>(&w_s[0][0]);
        for (int i = tid; i < (P_ * WINB_) / 4; i += 256)
            wz[i] = make_float4(0.f, 0.f, 0.f, 0.f);
        if (tid < P_) { rmin_s[tid] = 0x7fffffff; rmax_s[tid] = -1; }
    }
    __syncthreads();

    // ---- Phase A: collapse all 32*grid_h samples into per-bin row weights ----
    const int S = P_ * grid_h;
    for (int s = tid; s < S; s += 256) {
        const int   p       = s & (P_ - 1);
        const int   g       = s >> 5;
        const float bin_off = __fmaf_rn((float)p, bin_h, start);
        const float y       = __fmaf_rn((float)g + 0.5f, sub, bin_off);
        if (y >= -1.0f && y <= (float)LV_) {
            float yc = fmaxf(y, 0.0f);
            int ylo = (int)floorf(yc);
            int yhi; float ly;
            if (ylo >= LV_ - 1) {            // hi_case from reference
                ylo = LV_ - 1; yhi = LV_ - 1; ly = 0.0f;
            } else {
                yhi = ylo + 1; ly = yc - (float)ylo;
            }
            int rbp = (int)floorf(bin_off);
            rbp = min(max(rbp, 0), LV_ - 1);
            int i0 = min(max(ylo - rbp, 0), WINB_ - 1);  // guards smem
            int i1 = min(max(yhi - rbp, 0), WINB_ - 1);
            atomicAdd(&w_s[p][i0], 1.0f - ly);
            atomicAdd(&w_s[p][i1], ly);
            atomicMin(&rmin_s[p], ylo);
            atomicMax(&rmax_s[p], yhi);
        }
    }
    __syncthreads();

    const float invc = 1.0f / (float)cnt;
    const int   base = bidx[n] * LV_;

    // ---- Phase B: warp w handles bins 4w..4w+3; 32 lanes x 8 halves = row ----
    #pragma unroll
    for (int j = 0; j < 4; ++j) {
        const int b = (wid << 2) + j;

        const float bin_off = __fmaf_rn((float)b, bin_h, start);  // same expr as Phase A
        int rbp = (int)floorf(bin_off);
        rbp = min(max(rbp, 0), LV_ - 1);

        int rmin = rmin_s[b];
        int rmax = rmax_s[b];
        if (rmax < rmin) { rmin = 0; rmax = -1; }   // empty bin

        uint64_t a0 = 0ull, a1 = 0ull, a2 = 0ull, a3 = 0ull;   // packed f32x2 accs
        const float* wrow = &w_s[b][0];
        const uint4* fp = reinterpret_cast<const uint4*>(g_feat16)
                        + (size_t)(base + rmin) * (D_ / 8) + lane;

        #pragma unroll 2
        for (int r = rmin; r <= rmax; ++r) {
            const float wr = wrow[r - rbp];
            uint64_t wp;
            asm("mov.b64 %0, {%1, %1};" : "=l"(wp) : "f"(wr));

            uint4 u = *fp;
            fp += (D_ / 8);
            float2 v0 = __half22float2(*reinterpret_cast<__half2*>(&u.x));
            float2 v1 = __half22float2(*reinterpret_cast<__half2*>(&u.y));
            float2 v2 = __half22float2(*reinterpret_cast<__half2*>(&u.z));
            float2 v3 = __half22float2(*reinterpret_cast<__half2*>(&u.w));

            uint64_t p0, p1, p2, p3;
            asm("mov.b64 %0, {%1, %2};" : "=l"(p0) : "f"(v0.x), "f"(v0.y));
            asm("mov.b64 %0, {%1, %2};" : "=l"(p1) : "f"(v1.x), "f"(v1.y));
            asm("mov.b64 %0, {%1, %2};" : "=l"(p2) : "f"(v2.x), "f"(v2.y));
            asm("mov.b64 %0, {%1, %2};" : "=l"(p3) : "f"(v3.x), "f"(v3.y));

            asm("fma.rn.f32x2 %0, %1, %2, %0;" : "+l"(a0) : "l"(p0), "l"(wp));
            asm("fma.rn.f32x2 %0, %1, %2, %0;" : "+l"(a1) : "l"(p1), "l"(wp));
            asm("fma.rn.f32x2 %0, %1, %2, %0;" : "+l"(a2) : "l"(p2), "l"(wp));
            asm("fma.rn.f32x2 %0, %1, %2, %0;" : "+l"(a3) : "l"(p3), "l"(wp));
        }

        float o0, o1, o2, o3, o4, o5, o6, o7;
        asm("mov.b64 {%0, %1}, %2;" : "=f"(o0), "=f"(o1) : "l"(a0));
        asm("mov.b64 {%0, %1}, %2;" : "=f"(o2), "=f"(o3) : "l"(a1));
        asm("mov.b64 {%0, %1}, %2;" : "=f"(o4), "=f"(o5) : "l"(a2));
        asm("mov.b64 {%0, %1}, %2;" : "=f"(o6), "=f"(o7) : "l"(a3));

        float4 r0 = make_float4(o0 * invc, o1 * invc, o2 * invc, o3 * invc);
        float4 r1 = make_float4(o4 * invc, o5 * invc, o6 * invc, o7 * invc);
        float4* op = reinterpret_cast<float4*>(out)
                   + ((size_t)n * P_ + b) * (D_ / 4) + lane * 2;
        op[0] = r0;
        op[1] = r1;
    }
}

extern "C" void kernel_launch(void* const* d_in, const int* in_sizes, int n_in,
                              void* d_out, int out_size)
{
    const float* feat  = (const float*)d_in[0];   // [8, 4096, 256] f32
    const float* boxes = (const float*)d_in[1];   // [2048, 2] f32
    const int*   bidx  = (const int*)  d_in[2];   // [2048] i32
    float*       out   = (float*)d_out;           // [2048, 32, 256] f32

    cvt_kernel<<<(B_ * LV_ * D_ / 8) / 256, 256>>>(feat);
    roi_align1d_kernel<<<N_, 256>>>(boxes, bidx, out);
}

// round 7
// speedup vs baseline: 1.2612x; 1.2612x over previous
#include <cuda_runtime.h>
#include <cuda_fp16.h>
#include <cstdint>

// RoIAlign1D: B=8, LV=4096, D=256, N=2048 boxes, P=32 bins.
// R6: per-(box,bin) WARP (duration-uniform grid of 32768 x 64thr blocks).
// Warp = full 256-ch row (32 lanes x 8 halves, LDG.128). Accumulate in
// half2 via HFMA2 for 4-row chunks, promote to packed f32x2 accumulators.

#define B_    8
#define LV_   4096
#define D_    256
#define N_    2048
#define P_    32
#define WINB_ 136   // per-bin row window: bin_h<=128 -> <=132 rows + slack

// 16 MB fp16 copy of feat (static device scratch; no allocation APIs used)
__device__ __half g_feat16[B_ * LV_ * D_];

// ---- pre-pass: f32 -> f16, 8 floats per thread, fully coalesced ----
__global__ __launch_bounds__(256) void cvt_kernel(const float* __restrict__ feat)
{
    const int i = blockIdx.x * 256 + threadIdx.x;       // uint4 (8-half) index
    const float4* src = reinterpret_cast<const float4*>(feat) + 2 * (size_t)i;
    float4 v0 = src[0];
    float4 v1 = src[1];
    __half2 h0 = __floats2half2_rn(v0.x, v0.y);
    __half2 h1 = __floats2half2_rn(v0.z, v0.w);
    __half2 h2 = __floats2half2_rn(v1.x, v1.y);
    __half2 h3 = __floats2half2_rn(v1.z, v1.w);
    uint4 o;
    o.x = *reinterpret_cast<unsigned int*>(&h0);
    o.y = *reinterpret_cast<unsigned int*>(&h1);
    o.z = *reinterpret_cast<unsigned int*>(&h2);
    o.w = *reinterpret_cast<unsigned int*>(&h3);
    reinterpret_cast<uint4*>(g_feat16)[i] = o;
}

__global__ __launch_bounds__(64) void roi_align1d_kernel(
    const float* __restrict__ boxes,   // [N, 2]
    const int*   __restrict__ bidx,    // [N]
    float*       __restrict__ out)     // [N, P, D]
{
    __shared__ float    wf_s[2][WINB_];   // per-warp f32 weights (Phase A)
    __shared__ unsigned w2_s[2][WINB_];   // per-warp {h,h} half2 weights
    __shared__ int      rmin_s[2], rmax_s[2];

    const int tid  = threadIdx.x;      // 0..63
    const int wid  = tid >> 5;         // 0,1 -> independent (box,bin) pairs
    const int lane = tid & 31;

    const int pair = blockIdx.x * 2 + wid;   // 0 .. N*P-1
    const int n    = pair >> 5;              // box
    const int p    = pair & (P_ - 1);        // bin

    // ---- box/bin scalars ----
    const float y1     = boxes[2 * n];
    const float y2     = boxes[2 * n + 1];
    const float bin_h  = (y2 - y1) * (1.0f / (float)P_);
    const int   grid_h = (int)ceilf(bin_h);
    const int   cnt    = max(grid_h, 1);
    const float sub    = bin_h / (float)cnt;
    const float bin_off = (y1 - 0.5f) + (float)p * bin_h;

    int rbp = (int)floorf(bin_off);
    rbp = min(max(rbp, 0), LV_ - 1);

    // ---- zero my weight window ----
    float* wf = &wf_s[wid][0];
    #pragma unroll
    for (int i = lane; i < WINB_; i += 32) wf[i] = 0.0f;
    if (lane == 0) { rmin_s[wid] = 0x7fffffff; rmax_s[wid] = -1; }
    __syncwarp();

    // ---- Phase A: collapse samples into per-row bilinear weights ----
    for (int g = lane; g < grid_h; g += 32) {
        float y = bin_off + ((float)g + 0.5f) * sub;
        if (y >= -1.0f && y <= (float)LV_) {
            float yc = fmaxf(y, 0.0f);
            int ylo = (int)floorf(yc);
            int yhi; float ly;
            if (ylo >= LV_ - 1) {            // hi_case from reference
                ylo = LV_ - 1; yhi = LV_ - 1; ly = 0.0f;
            } else {
                yhi = ylo + 1; ly = yc - (float)ylo;
            }
            int i0 = min(max(ylo - rbp, 0), WINB_ - 1);  // guards smem (no-op math)
            int i1 = min(max(yhi - rbp, 0), WINB_ - 1);
            atomicAdd(&wf[i0], 1.0f - ly);
            atomicAdd(&wf[i1], ly);
            atomicMin(&rmin_s[wid], ylo);
            atomicMax(&rmax_s[wid], yhi);
        }
    }
    __syncwarp();

    int rmin = rmin_s[wid];
    int rmax = rmax_s[wid];
    if (rmax < rmin) { rmin = 0; rmax = -1; }   // empty bin -> zero output

    // ---- convert used weights to broadcast half2 ----
    unsigned* w2 = &w2_s[wid][0];
    const int wlen = (rmax >= rmin) ? (rmax - rbp + 1) : 0;
    for (int i = lane; i < wlen; i += 32) {
        __half  h  = __float2half_rn(wf[i]);
        __half2 hh = __half2half2(h);
        w2[i] = *reinterpret_cast<unsigned*>(&hh);
    }
    __syncwarp();

    const float invc = 1.0f / (float)cnt;
    const int   base = bidx[n] * LV_;

    // ---- Phase B: half2 MAC, chunk=4 rows, promote to f32x2 ----
    __half2 c0 = __float2half2_rn(0.f), c1 = c0, c2 = c0, c3 = c0;
    uint64_t A0 = 0ull, A1 = 0ull, A2 = 0ull, A3 = 0ull;   // packed f32x2 accs

    const uint4* fp = reinterpret_cast<const uint4*>(g_feat16)
                    + (size_t)(base + rmin) * (D_ / 8) + lane;
    const unsigned* w2row = w2 + (rmin - rbp);

    int r = rmin;
    for (; r + 3 <= rmax; r += 4) {
        #pragma unroll
        for (int k = 0; k < 4; ++k) {
            uint4 u = fp[k * (D_ / 8)];
            unsigned wv = w2row[r - rmin + k];
            __half2 w2v = *reinterpret_cast<__half2*>(&wv);
            c0 = __hfma2(*reinterpret_cast<__half2*>(&u.x), w2v, c0);
            c1 = __hfma2(*reinterpret_cast<__half2*>(&u.y), w2v, c1);
            c2 = __hfma2(*reinterpret_cast<__half2*>(&u.z), w2v, c2);
            c3 = __hfma2(*reinterpret_cast<__half2*>(&u.w), w2v, c3);
        }
        fp += 4 * (D_ / 8);

        // promote chunk partials to f32x2 accumulators, reset half2 accs
        float2 f0 = __half22float2(c0);
        float2 f1 = __half22float2(c1);
        float2 f2 = __half22float2(c2);
        float2 f3 = __half22float2(c3);
        uint64_t p0, p1, p2, p3;
        asm("mov.b64 %0, {%1, %2};" : "=l"(p0) : "f"(f0.x), "f"(f0.y));
        asm("mov.b64 %0, {%1, %2};" : "=l"(p1) : "f"(f1.x), "f"(f1.y));
        asm("mov.b64 %0, {%1, %2};" : "=l"(p2) : "f"(f2.x), "f"(f2.y));
        asm("mov.b64 %0, {%1, %2};" : "=l"(p3) : "f"(f3.x), "f"(f3.y));
        asm("add.rn.f32x2 %0, %0, %1;" : "+l"(A0) : "l"(p0));
        asm("add.rn.f32x2 %0, %0, %1;" : "+l"(A1) : "l"(p1));
        asm("add.rn.f32x2 %0, %0, %1;" : "+l"(A2) : "l"(p2));
        asm("add.rn.f32x2 %0, %0, %1;" : "+l"(A3) : "l"(p3));
        c0 = __float2half2_rn(0.f); c1 = c0; c2 = c0; c3 = c0;
    }
    for (; r <= rmax; ++r) {             // remainder rows (<=3)
        uint4 u = *fp;
        fp += (D_ / 8);
        unsigned wv = w2row[r - rmin];
        __half2 w2v = *reinterpret_cast<__half2*>(&wv);
        c0 = __hfma2(*reinterpret_cast<__half2*>(&u.x), w2v, c0);
        c1 = __hfma2(*reinterpret_cast<__half2*>(&u.y), w2v, c1);
        c2 = __hfma2(*reinterpret_cast<__half2*>(&u.z), w2v, c2);
        c3 = __hfma2(*reinterpret_cast<__half2*>(&u.w), w2v, c3);
    }
    {   // final promote
        float2 f0 = __half22float2(c0);
        float2 f1 = __half22float2(c1);
        float2 f2 = __half22float2(c2);
        float2 f3 = __half22float2(c3);
        uint64_t p0, p1, p2, p3;
        asm("mov.b64 %0, {%1, %2};" : "=l"(p0) : "f"(f0.x), "f"(f0.y));
        asm("mov.b64 %0, {%1, %2};" : "=l"(p1) : "f"(f1.x), "f"(f1.y));
        asm("mov.b64 %0, {%1, %2};" : "=l"(p2) : "f"(f2.x), "f"(f2.y));
        asm("mov.b64 %0, {%1, %2};" : "=l"(p3) : "f"(f3.x), "f"(f3.y));
        asm("add.rn.f32x2 %0, %0, %1;" : "+l"(A0) : "l"(p0));
        asm("add.rn.f32x2 %0, %0, %1;" : "+l"(A1) : "l"(p1));
        asm("add.rn.f32x2 %0, %0, %1;" : "+l"(A2) : "l"(p2));
        asm("add.rn.f32x2 %0, %0, %1;" : "+l"(A3) : "l"(p3));
    }

    // ---- unpack, normalize, store ----
    float o0, o1, o2, o3, o4, o5, o6, o7;
    asm("mov.b64 {%0, %1}, %2;" : "=f"(o0), "=f"(o1) : "l"(A0));
    asm("mov.b64 {%0, %1}, %2;" : "=f"(o2), "=f"(o3) : "l"(A1));
    asm("mov.b64 {%0, %1}, %2;" : "=f"(o4), "=f"(o5) : "l"(A2));
    asm("mov.b64 {%0, %1}, %2;" : "=f"(o6), "=f"(o7) : "l"(A3));

    float4 r0 = make_float4(o0 * invc, o1 * invc, o2 * invc, o3 * invc);
    float4 r1 = make_float4(o4 * invc, o5 * invc, o6 * invc, o7 * invc);
    float4* op = reinterpret_cast<float4*>(out)
               + (size_t)pair * (D_ / 4) + lane * 2;
    op[0] = r0;
    op[1] = r1;
}

extern "C" void kernel_launch(void* const* d_in, const int* in_sizes, int n_in,
                              void* d_out, int out_size)
{
    const float* feat  = (const float*)d_in[0];   // [8, 4096, 256] f32
    const float* boxes = (const float*)d_in[1];   // [2048, 2] f32
    const int*   bidx  = (const int*)  d_in[2];   // [2048] i32
    float*       out   = (float*)d_out;           // [2048, 32, 256] f32

    cvt_kernel<<<(B_ * LV_ * D_ / 8) / 256, 256>>>(feat);
    roi_align1d_kernel<<<(N_ * P_) / 2, 64>>>(boxes, bidx, out);
}

// round 8
// speedup vs baseline: 1.5026x; 1.1914x over previous
#include <cuda_runtime.h>
#include <cuda_fp16.h>
#include <cstdint>

// RoIAlign1D: B=8, LV=4096, D=256, N=2048 boxes, P=32 bins.
// R7: R3 block shape (block = one (box,bin), 64 thr, lane owns 4 channels,
// both warps on the same row) + R6 math (HFMA2 chunk-4 accumulation with
// packed f32x2 promotes). High occupancy + low instruction count.

#define B_    8
#define LV_   4096
#define D_    256
#define N_    2048
#define P_    32
#define WINB_ 136   // row window: bin_h<=128 -> <=132 rows + slack

// 16 MB fp16 copy of feat (static device scratch; no allocation APIs used)
__device__ __half g_feat16[B_ * LV_ * D_];

// ---- pre-pass: f32 -> f16, 8 floats per thread, fully coalesced ----
__global__ __launch_bounds__(256) void cvt_kernel(const float* __restrict__ feat)
{
    const int i = blockIdx.x * 256 + threadIdx.x;       // uint4 (8-half) index
    const float4* src = reinterpret_cast<const float4*>(feat) + 2 * (size_t)i;
    float4 v0 = src[0];
    float4 v1 = src[1];
    __half2 h0 = __floats2half2_rn(v0.x, v0.y);
    __half2 h1 = __floats2half2_rn(v0.z, v0.w);
    __half2 h2 = __floats2half2_rn(v1.x, v1.y);
    __half2 h3 = __floats2half2_rn(v1.z, v1.w);
    uint4 o;
    o.x = *reinterpret_cast<unsigned int*>(&h0);
    o.y = *reinterpret_cast<unsigned int*>(&h1);
    o.z = *reinterpret_cast<unsigned int*>(&h2);
    o.w = *reinterpret_cast<unsigned int*>(&h3);
    reinterpret_cast<uint4*>(g_feat16)[i] = o;
}

__global__ __launch_bounds__(64) void roi_align1d_kernel(
    const float* __restrict__ boxes,   // [N, 2]
    const int*   __restrict__ bidx,    // [N]
    float*       __restrict__ out)     // [N, P, D]
{
    __shared__ float    wf_s[WINB_];   // f32 weights (Phase A)
    __shared__ unsigned w2_s[WINB_];   // {h,h} half2 weights (Phase B)
    __shared__ int      rmin_s, rmax_s;

    const int blk = blockIdx.x;        // 0 .. N*P-1
    const int n   = blk >> 5;          // box
    const int p   = blk & (P_ - 1);    // bin
    const int tid = threadIdx.x;       // 0..63

    // ---- box/bin scalars ----
    const float y1     = boxes[2 * n];
    const float y2     = boxes[2 * n + 1];
    const float bin_h  = (y2 - y1) * (1.0f / (float)P_);
    const int   grid_h = (int)ceilf(bin_h);
    const int   cnt    = max(grid_h, 1);
    const float sub    = bin_h / (float)cnt;
    const float bin_off = (y1 - 0.5f) + (float)p * bin_h;

    int rbp = (int)floorf(bin_off);
    rbp = min(max(rbp, 0), LV_ - 1);

    // ---- zero the weight window ----
    #pragma unroll
    for (int i = tid; i < WINB_; i += 64) wf_s[i] = 0.0f;
    if (tid == 0) { rmin_s = 0x7fffffff; rmax_s = -1; }
    __syncthreads();

    // ---- Phase A: collapse samples into per-row bilinear weights ----
    for (int g = tid; g < grid_h; g += 64) {
        float y = bin_off + ((float)g + 0.5f) * sub;
        if (y >= -1.0f && y <= (float)LV_) {
            float yc = fmaxf(y, 0.0f);
            int ylo = (int)floorf(yc);
            int yhi; float ly;
            if (ylo >= LV_ - 1) {            // hi_case from reference
                ylo = LV_ - 1; yhi = LV_ - 1; ly = 0.0f;
            } else {
                yhi = ylo + 1; ly = yc - (float)ylo;
            }
            int i0 = min(max(ylo - rbp, 0), WINB_ - 1);  // guards smem (no-op math)
            int i1 = min(max(yhi - rbp, 0), WINB_ - 1);
            atomicAdd(&wf_s[i0], 1.0f - ly);
            atomicAdd(&wf_s[i1], ly);
            atomicMin(&rmin_s, ylo);
            atomicMax(&rmax_s, yhi);
        }
    }
    __syncthreads();

    int rmin = rmin_s;
    int rmax = rmax_s;
    if (rmax < rmin) { rmin = 0; rmax = -1; }   // empty bin -> zero output

    // ---- convert used weights to broadcast half2 ----
    const int wlen = (rmax >= rmin) ? (rmax - rbp + 1) : 0;
    for (int i = tid; i < wlen; i += 64) {
        __half  h  = __float2half_rn(wf_s[i]);
        __half2 hh = __half2half2(h);
        w2_s[i] = *reinterpret_cast<unsigned*>(&hh);
    }
    __syncthreads();

    const float invc = 1.0f / (float)cnt;
    const int   base = bidx[n] * LV_;

    // ---- Phase B: all 64 threads on the same row; lane owns 4 channels
    //      (uint2 = 2 half2). HFMA2 chunk-4, promote to packed f32x2. ----
    __half2  c0 = __float2half2_rn(0.f), c1 = c0;
    uint64_t A0 = 0ull, A1 = 0ull;               // packed f32x2 accumulators

    const uint2* fp = reinterpret_cast<const uint2*>(g_feat16)
                    + (size_t)(base + rmin) * (D_ / 4) + tid;
    const unsigned* w2row = w2_s + (rmin - rbp);

    int r = rmin;
    for (; r + 3 <= rmax; r += 4) {
        #pragma unroll
        for (int k = 0; k < 4; ++k) {
            uint2 u = fp[k * (D_ / 4)];
            unsigned wv = w2row[r - rmin + k];
            __half2 w2v = *reinterpret_cast<__half2*>(&wv);
            c0 = __hfma2(*reinterpret_cast<__half2*>(&u.x), w2v, c0);
            c1 = __hfma2(*reinterpret_cast<__half2*>(&u.y), w2v, c1);
        }
        fp += 4 * (D_ / 4);

        // promote chunk partials to f32x2 accumulators, reset half2 accs
        float2 f0 = __half22float2(c0);
        float2 f1 = __half22float2(c1);
        uint64_t p0, p1;
        asm("mov.b64 %0, {%1, %2};" : "=l"(p0) : "f"(f0.x), "f"(f0.y));
        asm("mov.b64 %0, {%1, %2};" : "=l"(p1) : "f"(f1.x), "f"(f1.y));
        asm("add.rn.f32x2 %0, %0, %1;" : "+l"(A0) : "l"(p0));
        asm("add.rn.f32x2 %0, %0, %1;" : "+l"(A1) : "l"(p1));
        c0 = __float2half2_rn(0.f); c1 = c0;
    }
    for (; r <= rmax; ++r) {             // remainder rows (<=3)
        uint2 u = *fp;
        fp += (D_ / 4);
        unsigned wv = w2row[r - rmin];
        __half2 w2v = *reinterpret_cast<__half2*>(&wv);
        c0 = __hfma2(*reinterpret_cast<__half2*>(&u.x), w2v, c0);
        c1 = __hfma2(*reinterpret_cast<__half2*>(&u.y), w2v, c1);
    }
    {   // final promote
        float2 f0 = __half22float2(c0);
        float2 f1 = __half22float2(c1);
        uint64_t p0, p1;
        asm("mov.b64 %0, {%1, %2};" : "=l"(p0) : "f"(f0.x), "f"(f0.y));
        asm("mov.b64 %0, {%1, %2};" : "=l"(p1) : "f"(f1.x), "f"(f1.y));
        asm("add.rn.f32x2 %0, %0, %1;" : "+l"(A0) : "l"(p0));
        asm("add.rn.f32x2 %0, %0, %1;" : "+l"(A1) : "l"(p1));
    }

    // ---- unpack, normalize, store ----
    float o0, o1, o2, o3;
    asm("mov.b64 {%0, %1}, %2;" : "=f"(o0), "=f"(o1) : "l"(A0));
    asm("mov.b64 {%0, %1}, %2;" : "=f"(o2), "=f"(o3) : "l"(A1));

    float4 o = make_float4(o0 * invc, o1 * invc, o2 * invc, o3 * invc);
    reinterpret_cast<float4*>(out)[(size_t)blk * (D_ / 4) + tid] = o;
}

extern "C" void kernel_launch(void* const* d_in, const int* in_sizes, int n_in,
                              void* d_out, int out_size)
{
    const float* feat  = (const float*)d_in[0];   // [8, 4096, 256] f32
    const float* boxes = (const float*)d_in[1];   // [2048, 2] f32
    const int*   bidx  = (const int*)  d_in[2];   // [2048] i32
    float*       out   = (float*)d_out;           // [2048, 32, 256] f32

    cvt_kernel<<<(B_ * LV_ * D_ / 8) / 256, 256>>>(feat);
    roi_align1d_kernel<<<N_ * P_, 64>>>(boxes, bidx, out);
}

// round 10
// speedup vs baseline: 1.5483x; 1.0304x over previous
#include <cuda_runtime.h>
#include <cuda_fp16.h>
#include <cstdint>

// RoIAlign1D: B=8, LV=4096, D=256, N=2048 boxes, P=32 bins.
// R8: L1tex-wavefront bound -> strip non-LDG l1tex work:
//  - window starts at rbp, zero-padded to multiple of 4 rows (no remainder,
//    pointer-only loop), feat scratch padded +4 rows for safe tail reads
//  - weights: ONE broadcast LDS.128 per 4-row chunk (4 half2 weights)
//  - 1/count folded into the fp16 weights
//  - explicit 4-deep load batch (MLP=4), HFMA2 chunk-4 -> f32x2 promote

#define B_    8
#define LV_   4096
#define D_    256
#define N_    2048
#define P_    32
#define WINB_ 136   // padded window: wlen<=132, ceil4<=132, +slack (mult of 4)

// fp16 feat copy + 4-row tail pad (device globals are zero-initialized)
__device__ __half g_feat16[(B_ * LV_ + 4) * D_];

// ---- pre-pass: f32 -> f16, 8 floats per thread, fully coalesced ----
__global__ __launch_bounds__(256) void cvt_kernel(const float* __restrict__ feat)
{
    const int i = blockIdx.x * 256 + threadIdx.x;       // uint4 (8-half) index
    const float4* src = reinterpret_cast<const float4*>(feat) + 2 * (size_t)i;
    float4 v0 = src[0];
    float4 v1 = src[1];
    __half2 h0 = __floats2half2_rn(v0.x, v0.y);
    __half2 h1 = __floats2half2_rn(v0.z, v0.w);
    __half2 h2 = __floats2half2_rn(v1.x, v1.y);
    __half2 h3 = __floats2half2_rn(v1.z, v1.w);
    uint4 o;
    o.x = *reinterpret_cast<unsigned int*>(&h0);
    o.y = *reinterpret_cast<unsigned int*>(&h1);
    o.z = *reinterpret_cast<unsigned int*>(&h2);
    o.w = *reinterpret_cast<unsigned int*>(&h3);
    reinterpret_cast<uint4*>(g_feat16)[i] = o;
}

__device__ __forceinline__ __half2 u2h(unsigned v)
{
    return *reinterpret_cast<__half2*>(&v);
}

__global__ __launch_bounds__(64) void roi_align1d_kernel(
    const float* __restrict__ boxes,   // [N, 2]
    const int*   __restrict__ bidx,    // [N]
    float*       __restrict__ out)     // [N, P, D]
{
    __shared__ float                 wf_s[WINB_];  // f32 weights (Phase A)
    __shared__ __align__(16) unsigned w2_s[WINB_]; // {h,h} half2 weights * invc
    __shared__ int                   rmax_s;

    const int blk = blockIdx.x;        // 0 .. N*P-1
    const int n   = blk >> 5;          // box
    const int p   = blk & (P_ - 1);    // bin
    const int tid = threadIdx.x;       // 0..63

    // ---- box/bin scalars ----
    const float y1     = boxes[2 * n];
    const float y2     = boxes[2 * n + 1];
    const float bin_h  = (y2 - y1) * (1.0f / (float)P_);
    const int   grid_h = (int)ceilf(bin_h);
    const int   cnt    = max(grid_h, 1);
    const float sub    = bin_h / (float)cnt;
    const float bin_off = (y1 - 0.5f) + (float)p * bin_h;
    const float invc   = 1.0f / (float)cnt;

    int rbp = (int)floorf(bin_off);
    rbp = min(max(rbp, 0), LV_ - 1);

    // ---- zero the weight window ----
    #pragma unroll
    for (int i = tid; i < WINB_; i += 64) wf_s[i] = 0.0f;
    if (tid == 0) rmax_s = -1;
    __syncthreads();

    // ---- Phase A: collapse samples into per-row bilinear weights ----
    for (int g = tid; g < grid_h; g += 64) {
        float y = bin_off + ((float)g + 0.5f) * sub;
        if (y >= -1.0f && y <= (float)LV_) {
            float yc = fmaxf(y, 0.0f);
            int ylo = (int)floorf(yc);
            int yhi; float ly;
            if (ylo >= LV_ - 1) {            // hi_case from reference
                ylo = LV_ - 1; yhi = LV_ - 1; ly = 0.0f;
            } else {
                yhi = ylo + 1; ly = yc - (float)ylo;
            }
            int i0 = min(max(ylo - rbp, 0), WINB_ - 1);  // guards smem (no-op math)
            int i1 = min(max(yhi - rbp, 0), WINB_ - 1);
            atomicAdd(&wf_s[i0], 1.0f - ly);
            atomicAdd(&wf_s[i1], ly);
            atomicMax(&rmax_s, yhi);
        }
    }
    __syncthreads();

    // ---- convert (weight * invc) to broadcast half2 over padded window ----
    #pragma unroll
    for (int i = tid; i < WINB_; i += 64) {
        __half  h  = __float2half_rn(wf_s[i] * invc);
        __half2 hh = __half2half2(h);
        w2_s[i] = *reinterpret_cast<unsigned*>(&hh);
    }
    __syncthreads();

    const int rmax = rmax_s;
    const int wlen = rmax - rbp + 1;                    // <=0 if empty bin
    const int nch  = (wlen > 0) ? ((wlen + 3) >> 2) : 0; // 4-row chunks (padded)

    const int base = bidx[n] * LV_;

    // ---- Phase B: all 64 threads on same row; lane owns 4 channels ----
    __half2  c0 = __float2half2_rn(0.f), c1 = c0;
    uint64_t A0 = 0ull, A1 = 0ull;               // packed f32x2 accumulators

    const uint2* fp = reinterpret_cast<const uint2*>(g_feat16)
                    + (size_t)(base + rbp) * (D_ / 4) + tid;
    const uint4* wq = reinterpret_cast<const uint4*>(w2_s);

    for (int t = nch; t > 0; --t) {
        const uint4 wv = *wq++;                  // 4 rows' weights (broadcast)
        const uint2 u0 = fp[0 * (D_ / 4)];
        const uint2 u1 = fp[1 * (D_ / 4)];
        const uint2 u2 = fp[2 * (D_ / 4)];
        const uint2 u3 = fp[3 * (D_ / 4)];
        fp += 4 * (D_ / 4);

        c0 = __hfma2(u2h(u0.x), u2h(wv.x), c0);
        c1 = __hfma2(u2h(u0.y), u2h(wv.x), c1);
        c0 = __hfma2(u2h(u1.x), u2h(wv.y), c0);
        c1 = __hfma2(u2h(u1.y), u2h(wv.y), c1);
        c0 = __hfma2(u2h(u2.x), u2h(wv.z), c0);
        c1 = __hfma2(u2h(u2.y), u2h(wv.z), c1);
        c0 = __hfma2(u2h(u3.x), u2h(wv.w), c0);
        c1 = __hfma2(u2h(u3.y), u2h(wv.w), c1);

        // promote chunk partials to f32x2 accumulators, reset half2 accs
        float2 f0 = __half22float2(c0);
        float2 f1 = __half22float2(c1);
        uint64_t p0, p1;
        asm("mov.b64 %0, {%1, %2};" : "=l"(p0) : "f"(f0.x), "f"(f0.y));
        asm("mov.b64 %0, {%1, %2};" : "=l"(p1) : "f"(f1.x), "f"(f1.y));
        asm("add.rn.f32x2 %0, %0, %1;" : "+l"(A0) : "l"(p0));
        asm("add.rn.f32x2 %0, %0, %1;" : "+l"(A1) : "l"(p1));
        c0 = __float2half2_rn(0.f); c1 = c0;
    }

    // ---- unpack, store (invc already folded into weights) ----
    float o0, o1, o2, o3;
    asm("mov.b64 {%0, %1}, %2;" : "=f"(o0), "=f"(o1) : "l"(A0));
    asm("mov.b64 {%0, %1}, %2;" : "=f"(o2), "=f"(o3) : "l"(A1));

    float4 o = make_float4(o0, o1, o2, o3);
    reinterpret_cast<float4*>(out)[(size_t)blk * (D_ / 4) + tid] = o;
}

extern "C" void kernel_launch(void* const* d_in, const int* in_sizes, int n_in,
                              void* d_out, int out_size)
{
    const float* feat  = (const float*)d_in[0];   // [8, 4096, 256] f32
    const float* boxes = (const float*)d_in[1];   // [2048, 2] f32
    const int*   bidx  = (const int*)  d_in[2];   // [2048] i32
    float*       out   = (float*)d_out;           // [2048, 32, 256] f32

    cvt_kernel<<<(B_ * LV_ * D_ / 8) / 256, 256>>>(feat);
    roi_align1d_kernel<<<N_ * P_, 64>>>(boxes, bidx, out);
}

// round 14
// speedup vs baseline: 1.6301x; 1.0528x over previous
#include <cuda_runtime.h>
#include <cuda_fp16.h>
#include <cstdint>

// RoIAlign1D: B=8, LV=4096, D=256, N=2048 boxes, P=32 bins.
// R11: R10 occupancy fix, corrected. The R10 in-place weight conversion put
// __syncthreads() inside a divergent loop (UB -> inf). The barriers were
// unnecessary: each element is read+overwritten by the SAME thread. Now:
// one barrier after Phase A, barrier-free in-place convert, one barrier
// before Phase B. Everything else identical to R10:
//  - __launch_bounds__(64, 32) forcing <=32 regs (occ target ~90%)
//  - single smem weight buffer (f32 Phase A -> packed half2 in place)
//  - rbp-anchored window, R8 inner loop (LDS.128 weights, 4-deep LDG batch,
//    HFMA2 chunk-4 -> packed f32x2 promote), invc folded into weights.

#define B_    8
#define LV_   4096
#define D_    256
#define N_    2048
#define P_    32
#define WINB_ 136   // padded window: wlen<=132, ceil4<=132, +slack (mult of 4)

// fp16 feat copy + 4-row tail pad (device globals are zero-initialized)
__device__ __half g_feat16[(B_ * LV_ + 4) * D_];

// ---- pre-pass: f32 -> f16, 8 floats per thread, fully coalesced ----
__global__ __launch_bounds__(256) void cvt_kernel(const float* __restrict__ feat)
{
    const int i = blockIdx.x * 256 + threadIdx.x;       // uint4 (8-half) index
    const float4* src = reinterpret_cast<const float4*>(feat) + 2 * (size_t)i;
    float4 v0 = src[0];
    float4 v1 = src[1];
    __half2 h0 = __floats2half2_rn(v0.x, v0.y);
    __half2 h1 = __floats2half2_rn(v0.z, v0.w);
    __half2 h2 = __floats2half2_rn(v1.x, v1.y);
    __half2 h3 = __floats2half2_rn(v1.z, v1.w);
    uint4 o;
    o.x = *reinterpret_cast<unsigned int*>(&h0);
    o.y = *reinterpret_cast<unsigned int*>(&h1);
    o.z = *reinterpret_cast<unsigned int*>(&h2);
    o.w = *reinterpret_cast<unsigned int*>(&h3);
    reinterpret_cast<uint4*>(g_feat16)[i] = o;
}

__device__ __forceinline__ __half2 u2h(unsigned v)
{
    return *reinterpret_cast<__half2*>(&v);
}

__global__ __launch_bounds__(64, 32) void roi_align1d_kernel(
    const float* __restrict__ boxes,   // [N, 2]
    const int*   __restrict__ bidx,    // [N]
    float*       __restrict__ out)     // [N, P, D]
{
    // single buffer: f32 weights during Phase A, packed half2 after convert
    __shared__ __align__(16) unsigned w_s[WINB_];
    __shared__ int rmax_s;

    const int blk = blockIdx.x;        // 0 .. N*P-1
    const int n   = blk >> 5;          // box
    const int p   = blk & (P_ - 1);    // bin
    const int tid = threadIdx.x;       // 0..63

    // ---- box/bin scalars ----
    const float y1     = boxes[2 * n];
    const float y2     = boxes[2 * n + 1];
    const float bin_h  = (y2 - y1) * (1.0f / (float)P_);
    const int   grid_h = (int)ceilf(bin_h);
    const int   cnt    = max(grid_h, 1);
    const float sub    = bin_h / (float)cnt;
    const float bin_off = (y1 - 0.5f) + (float)p * bin_h;
    const float invc   = 1.0f / (float)cnt;

    int rbp = (int)floorf(bin_off);
    rbp = min(max(rbp, 0), LV_ - 1);

    // ---- zero the weight window (as f32) ----
    float* wf = reinterpret_cast<float*>(w_s);
    #pragma unroll
    for (int i = tid; i < WINB_; i += 64) wf[i] = 0.0f;
    if (tid == 0) rmax_s = -1;
    __syncthreads();

    // ---- Phase A: collapse samples into per-row bilinear weights ----
    for (int g = tid; g < grid_h; g += 64) {
        float y = bin_off + ((float)g + 0.5f) * sub;
        if (y >= -1.0f && y <= (float)LV_) {
            float yc = fmaxf(y, 0.0f);
            int ylo = (int)floorf(yc);
            int yhi; float ly;
            if (ylo >= LV_ - 1) {            // hi_case from reference
                ylo = LV_ - 1; yhi = LV_ - 1; ly = 0.0f;
            } else {
                yhi = ylo + 1; ly = yc - (float)ylo;
            }
            int i0 = min(max(ylo - rbp, 0), WINB_ - 1);  // guards smem (no-op math)
            int i1 = min(max(yhi - rbp, 0), WINB_ - 1);
            atomicAdd(&wf[i0], 1.0f - ly);
            atomicAdd(&wf[i1], ly);
            atomicMax(&rmax_s, yhi);
        }
    }
    __syncthreads();   // Phase A complete; every element now owned by one thread

    // ---- convert (weight * invc) to broadcast half2, IN PLACE ----
    // Each element i is read (f32) and overwritten (half2) by the SAME
    // thread; no cross-thread hazard, so no barriers inside the loop.
    #pragma unroll
    for (int i = tid; i < WINB_; i += 64) {
        float w = wf[i] * invc;
        __half  h  = __float2half_rn(w);
        __half2 hh = __half2half2(h);
        w_s[i] = *reinterpret_cast<unsigned*>(&hh);
    }
    __syncthreads();   // converted weights visible to all before Phase B

    const int wlen = rmax_s - rbp + 1;                   // <=0 if empty bin
    const int nch  = (wlen > 0) ? ((wlen + 3) >> 2) : 0; // 4-row chunks (padded)

    // ---- Phase B: all 64 threads on same row; lane owns 4 channels ----
    __half2  c0 = __float2half2_rn(0.f), c1 = c0;
    uint64_t A0 = 0ull, A1 = 0ull;               // packed f32x2 accumulators

    const uint2* fp = reinterpret_cast<const uint2*>(g_feat16)
                    + (size_t)(bidx[n] * LV_ + rbp) * (D_ / 4) + tid;
    const uint4* wq = reinterpret_cast<const uint4*>(w_s);

    for (int t = nch; t > 0; --t) {
        const uint4 wv = *wq++;                  // 4 rows' weights (broadcast)
        const uint2 u0 = fp[0 * (D_ / 4)];
        const uint2 u1 = fp[1 * (D_ / 4)];
        const uint2 u2 = fp[2 * (D_ / 4)];
        const uint2 u3 = fp[3 * (D_ / 4)];
        fp += 4 * (D_ / 4);

        c0 = __hfma2(u2h(u0.x), u2h(wv.x), c0);
        c1 = __hfma2(u2h(u0.y), u2h(wv.x), c1);
        c0 = __hfma2(u2h(u1.x), u2h(wv.y), c0);
        c1 = __hfma2(u2h(u1.y), u2h(wv.y), c1);
        c0 = __hfma2(u2h(u2.x), u2h(wv.z), c0);
        c1 = __hfma2(u2h(u2.y), u2h(wv.z), c1);
        c0 = __hfma2(u2h(u3.x), u2h(wv.w), c0);
        c1 = __hfma2(u2h(u3.y), u2h(wv.w), c1);

        // promote chunk partials to f32x2 accumulators, reset half2 accs
        float2 f0 = __half22float2(c0);
        float2 f1 = __half22float2(c1);
        uint64_t p0, p1;
        asm("mov.b64 %0, {%1, %2};" : "=l"(p0) : "f"(f0.x), "f"(f0.y));
        asm("mov.b64 %0, {%1, %2};" : "=l"(p1) : "f"(f1.x), "f"(f1.y));
        asm("add.rn.f32x2 %0, %0, %1;" : "+l"(A0) : "l"(p0));
        asm("add.rn.f32x2 %0, %0, %1;" : "+l"(A1) : "l"(p1));
        c0 = __float2half2_rn(0.f); c1 = c0;
    }

    // ---- unpack, store (invc already folded into weights) ----
    float o0, o1, o2, o3;
    asm("mov.b64 {%0, %1}, %2;" : "=f"(o0), "=f"(o1) : "l"(A0));
    asm("mov.b64 {%0, %1}, %2;" : "=f"(o2), "=f"(o3) : "l"(A1));

    float4 o = make_float4(o0, o1, o2, o3);
    reinterpret_cast<float4*>(out)[(size_t)blk * (D_ / 4) + tid] = o;
}

extern "C" void kernel_launch(void* const* d_in, const int* in_sizes, int n_in,
                              void* d_out, int out_size)
{
    const float* feat  = (const float*)d_in[0];   // [8, 4096, 256] f32
    const float* boxes = (const float*)d_in[1];   // [2048, 2] f32
    const int*   bidx  = (const int*)  d_in[2];   // [2048] i32
    float*       out   = (float*)d_out;           // [2048, 32, 256] f32

    cvt_kernel<<<(B_ * LV_ * D_ / 8) / 256, 256>>>(feat);
    roi_align1d_kernel<<<N_ * P_, 64>>>(boxes, bidx, out);
}

// round 16
// speedup vs baseline: 1.6352x; 1.0032x over previous
#include <cuda_runtime.h>
#include <cuda_fp16.h>
#include <cstdint>

// RoIAlign1D: B=8, LV=4096, D=256, N=2048 boxes, P=32 bins.
// R14: atomic-free Phase A. Each thread OWNS window rows and scans only the
// samples that can touch them (range via arithmetic inversion n(c)); each
// sample's weight uses the byte-identical reference formula, so accuracy is
// unchanged. Deletes all smem atomics (~35% of l1tex), the zero pass, the
// convert pass, and 2 of 3 barriers. Phase B identical to R11.

#define B_    8
#define LV_   4096
#define D_    256
#define N_    2048
#define P_    32
#define WINB_ 136   // padded window: wlen<=132, mult of 4

// fp16 feat copy + 4-row tail pad (device globals are zero-initialized)
__device__ __half g_feat16[(B_ * LV_ + 4) * D_];

// ---- pre-pass: f32 -> f16, 8 floats per thread, fully coalesced ----
__global__ __launch_bounds__(256) void cvt_kernel(const float* __restrict__ feat)
{
    const int i = blockIdx.x * 256 + threadIdx.x;       // uint4 (8-half) index
    const float4* src = reinterpret_cast<const float4*>(feat) + 2 * (size_t)i;
    float4 v0 = src[0];
    float4 v1 = src[1];
    __half2 h0 = __floats2half2_rn(v0.x, v0.y);
    __half2 h1 = __floats2half2_rn(v0.z, v0.w);
    __half2 h2 = __floats2half2_rn(v1.x, v1.y);
    __half2 h3 = __floats2half2_rn(v1.z, v1.w);
    uint4 o;
    o.x = *reinterpret_cast<unsigned int*>(&h0);
    o.y = *reinterpret_cast<unsigned int*>(&h1);
    o.z = *reinterpret_cast<unsigned int*>(&h2);
    o.w = *reinterpret_cast<unsigned int*>(&h3);
    reinterpret_cast<uint4*>(g_feat16)[i] = o;
}

__device__ __forceinline__ __half2 u2h(unsigned v)
{
    return *reinterpret_cast<__half2*>(&v);
}

__global__ __launch_bounds__(64, 32) void roi_align1d_kernel(
    const float* __restrict__ boxes,   // [N, 2]
    const int*   __restrict__ bidx,    // [N]
    float*       __restrict__ out)     // [N, P, D]
{
    __shared__ __align__(16) unsigned w_s[WINB_];   // packed half2 weights*invc

    const int blk = blockIdx.x;        // 0 .. N*P-1
    const int n   = blk >> 5;          // box
    const int p   = blk & (P_ - 1);    // bin
    const int tid = threadIdx.x;       // 0..63

    // ---- box/bin scalars ----
    const float y1     = boxes[2 * n];
    const float y2     = boxes[2 * n + 1];
    const float bin_h  = (y2 - y1) * (1.0f / (float)P_);
    const int   G      = (int)ceilf(bin_h);          // grid_h
    const int   cnt    = max(G, 1);
    const float sub    = bin_h / (float)cnt;
    const float bin_off = (y1 - 0.5f) + (float)p * bin_h;
    const float invc   = 1.0f / (float)cnt;

    int rbp = (int)floorf(bin_off);
    rbp = min(max(rbp, 0), LV_ - 1);

    // ---- analytic rmax (y is increasing in g; last sample bounds the window)
    int nch = 0;
    if (G > 0) {
        float ylast = bin_off + ((float)G - 0.5f) * sub;   // g = G-1
        float yc    = fmaxf(ylast, 0.0f);
        int   ylo   = (int)floorf(yc);
        int   rmax  = (ylo >= LV_ - 1) ? (LV_ - 1) : (ylo + 1);
        nch = (rmax - rbp + 4) >> 2;     // ceil((rmax-rbp+1)/4)
        nch = min(nch, WINB_ / 4);
    }
    const int   nrows   = nch * 4;
    const float inv_sub = 1.0f / sub;    // only used when G > 0 (nrows > 0)

    // ---- Phase A (atomic-free): thread owns rows, scans candidate samples.
    // n(c) = #samples with y < c, via inversion; per-sample weight uses the
    // exact reference formula (tent vanishes at the gate boundaries).
    for (int i = tid; i < nrows; i += 64) {
        const int r = rbp + i;

        float ql = ((float)(r - 1) - bin_off) * inv_sub - 0.5f;
        float qh = ((float)(r + 1) - bin_off) * inv_sub - 0.5f;
        ql = fminf(fmaxf(ql, 0.0f), (float)G);   // NaN/inf-safe clamps
        qh = fminf(fmaxf(qh, 0.0f), (float)G);
        const int glo = (int)ceilf(ql);
        const int ghi = (int)ceilf(qh);

        float w = 0.0f;
        for (int g = glo; g < ghi; ++g) {        // <= ~5 iterations (sub > 1/2)
            float y = bin_off + ((float)g + 0.5f) * sub;
            if (y >= -1.0f && y <= (float)LV_) {
                float yc = fmaxf(y, 0.0f);
                int ylo = (int)floorf(yc);
                int yhi; float ly;
                if (ylo >= LV_ - 1) {            // hi_case from reference
                    ylo = LV_ - 1; yhi = LV_ - 1; ly = 0.0f;
                } else {
                    yhi = ylo + 1; ly = yc - (float)ylo;
                }
                if (ylo == r) w += 1.0f - ly;
                if (yhi == r) w += ly;
            }
        }

        __half  h  = __float2half_rn(w * invc);
        __half2 hh = __half2half2(h);
        w_s[i] = *reinterpret_cast<unsigned*>(&hh);
    }
    __syncthreads();   // weights visible before Phase B

    // ---- Phase B: all 64 threads on same row; lane owns 4 channels ----
    __half2  c0 = __float2half2_rn(0.f), c1 = c0;
    uint64_t A0 = 0ull, A1 = 0ull;               // packed f32x2 accumulators

    const uint2* fp = reinterpret_cast<const uint2*>(g_feat16)
                    + (size_t)(bidx[n] * LV_ + rbp) * (D_ / 4) + tid;
    const uint4* wq = reinterpret_cast<const uint4*>(w_s);

    for (int t = nch; t > 0; --t) {
        const uint4 wv = *wq++;                  // 4 rows' weights (broadcast)
        const uint2 u0 = fp[0 * (D_ / 4)];
        const uint2 u1 = fp[1 * (D_ / 4)];
        const uint2 u2 = fp[2 * (D_ / 4)];
        const uint2 u3 = fp[3 * (D_ / 4)];
        fp += 4 * (D_ / 4);

        c0 = __hfma2(u2h(u0.x), u2h(wv.x), c0);
        c1 = __hfma2(u2h(u0.y), u2h(wv.x), c1);
        c0 = __hfma2(u2h(u1.x), u2h(wv.y), c0);
        c1 = __hfma2(u2h(u1.y), u2h(wv.y), c1);
        c0 = __hfma2(u2h(u2.x), u2h(wv.z), c0);
        c1 = __hfma2(u2h(u2.y), u2h(wv.z), c1);
        c0 = __hfma2(u2h(u3.x), u2h(wv.w), c0);
        c1 = __hfma2(u2h(u3.y), u2h(wv.w), c1);

        // promote chunk partials to f32x2 accumulators, reset half2 accs
        float2 f0 = __half22float2(c0);
        float2 f1 = __half22float2(c1);
        uint64_t p0, p1;
        asm("mov.b64 %0, {%1, %2};" : "=l"(p0) : "f"(f0.x), "f"(f0.y));
        asm("mov.b64 %0, {%1, %2};" : "=l"(p1) : "f"(f1.x), "f"(f1.y));
        asm("add.rn.f32x2 %0, %0, %1;" : "+l"(A0) : "l"(p0));
        asm("add.rn.f32x2 %0, %0, %1;" : "+l"(A1) : "l"(p1));
        c0 = __float2half2_rn(0.f); c1 = c0;
    }

    // ---- unpack, store (invc already folded into weights) ----
    float o0, o1, o2, o3;
    asm("mov.b64 {%0, %1}, %2;" : "=f"(o0), "=f"(o1) : "l"(A0));
    asm("mov.b64 {%0, %1}, %2;" : "=f"(o2), "=f"(o3) : "l"(A1));

    float4 o = make_float4(o0, o1, o2, o3);
    reinterpret_cast<float4*>(out)[(size_t)blk * (D_ / 4) + tid] = o;
}

extern "C" void kernel_launch(void* const* d_in, const int* in_sizes, int n_in,
                              void* d_out, int out_size)
{
    const float* feat  = (const float*)d_in[0];   // [8, 4096, 256] f32
    const float* boxes = (const float*)d_in[1];   // [2048, 2] f32
    const int*   bidx  = (const int*)  d_in[2];   // [2048] i32
    float*       out   = (float*)d_out;           // [2048, 32, 256] f32

    cvt_kernel<<<(B_ * LV_ * D_ / 8) / 256, 256>>>(feat);
    roi_align1d_kernel<<<N_ * P_, 64>>>(boxes, bidx, out);
}

// round 17
// speedup vs baseline: 1.6730x; 1.0231x over previous
#include <cuda_runtime.h>
#include <cuda_fp16.h>
#include <cstdint>

// RoIAlign1D: B=8, LV=4096, D=256, N=2048 boxes, P=32 bins.
// R16: latency-bound at MLP=4 -> chunk 4 -> 8. Eight LDG.64 batched before
// any HFMA2 (MLP=8), promote/loop overhead halved per row, weight LDS via
// two LDS.128 per 8 rows. launch_bounds(64,24) (<=42 regs) since the
// R8/R11 occupancy A/B showed occ 66 vs 88 is ~flat. Feat pad +8 rows
// (zero-init) so the padded tail reads 0 with weight 0.

#define B_    8
#define LV_   4096
#define D_    256
#define N_    2048
#define P_    32
#define WINB_ 136   // padded window: wlen<=133 -> ceil8 = 136 exactly (8*17)

// fp16 feat copy + 8-row tail pad (device globals are zero-initialized)
__device__ __half g_feat16[(B_ * LV_ + 8) * D_];

// ---- pre-pass: f32 -> f16, 8 floats per thread, fully coalesced ----
__global__ __launch_bounds__(256) void cvt_kernel(const float* __restrict__ feat)
{
    const int i = blockIdx.x * 256 + threadIdx.x;       // uint4 (8-half) index
    const float4* src = reinterpret_cast<const float4*>(feat) + 2 * (size_t)i;
    float4 v0 = src[0];
    float4 v1 = src[1];
    __half2 h0 = __floats2half2_rn(v0.x, v0.y);
    __half2 h1 = __floats2half2_rn(v0.z, v0.w);
    __half2 h2 = __floats2half2_rn(v1.x, v1.y);
    __half2 h3 = __floats2half2_rn(v1.z, v1.w);
    uint4 o;
    o.x = *reinterpret_cast<unsigned int*>(&h0);
    o.y = *reinterpret_cast<unsigned int*>(&h1);
    o.z = *reinterpret_cast<unsigned int*>(&h2);
    o.w = *reinterpret_cast<unsigned int*>(&h3);
    reinterpret_cast<uint4*>(g_feat16)[i] = o;
}

__device__ __forceinline__ __half2 u2h(unsigned v)
{
    return *reinterpret_cast<__half2*>(&v);
}

__global__ __launch_bounds__(64, 24) void roi_align1d_kernel(
    const float* __restrict__ boxes,   // [N, 2]
    const int*   __restrict__ bidx,    // [N]
    float*       __restrict__ out)     // [N, P, D]
{
    __shared__ __align__(16) unsigned w_s[WINB_];   // packed half2 weights*invc

    const int blk = blockIdx.x;        // 0 .. N*P-1
    const int n   = blk >> 5;          // box
    const int p   = blk & (P_ - 1);    // bin
    const int tid = threadIdx.x;       // 0..63

    // ---- box/bin scalars ----
    const float y1     = boxes[2 * n];
    const float y2     = boxes[2 * n + 1];
    const float bin_h  = (y2 - y1) * (1.0f / (float)P_);
    const int   G      = (int)ceilf(bin_h);          // grid_h
    const int   cnt    = max(G, 1);
    const float sub    = bin_h / (float)cnt;
    const float bin_off = (y1 - 0.5f) + (float)p * bin_h;
    const float invc   = 1.0f / (float)cnt;

    int rbp = (int)floorf(bin_off);
    rbp = min(max(rbp, 0), LV_ - 1);

    // ---- analytic rmax (y increasing in g; last sample bounds the window) ----
    int nch = 0;                                     // 8-row chunks
    if (G > 0) {
        float ylast = bin_off + ((float)G - 0.5f) * sub;   // g = G-1
        float yc    = fmaxf(ylast, 0.0f);
        int   ylo   = (int)floorf(yc);
        int   rmax  = (ylo >= LV_ - 1) ? (LV_ - 1) : (ylo + 1);
        nch = (rmax - rbp + 8) >> 3;     // ceil((rmax-rbp+1)/8)
        nch = min(nch, WINB_ / 8);
    }
    const int   nrows   = nch * 8;
    const float inv_sub = 1.0f / sub;    // only used when G > 0 (nrows > 0)

    // ---- Phase A (atomic-free): thread owns rows, scans candidate samples.
    // Per-sample weight uses the exact reference formula; the inversion only
    // gates which samples are scanned (tent vanishes at gate boundaries).
    for (int i = tid; i < nrows; i += 64) {
        const int r = rbp + i;

        float ql = ((float)(r - 1) - bin_off) * inv_sub - 0.5f;
        float qh = ((float)(r + 1) - bin_off) * inv_sub - 0.5f;
        ql = fminf(fmaxf(ql, 0.0f), (float)G);   // NaN/inf-safe clamps
        qh = fminf(fmaxf(qh, 0.0f), (float)G);
        const int glo = (int)ceilf(ql);
        const int ghi = (int)ceilf(qh);

        float w = 0.0f;
        for (int g = glo; g < ghi; ++g) {        // <= ~5 iterations (sub > 1/2)
            float y = bin_off + ((float)g + 0.5f) * sub;
            if (y >= -1.0f && y <= (float)LV_) {
                float yc = fmaxf(y, 0.0f);
                int ylo = (int)floorf(yc);
                int yhi; float ly;
                if (ylo >= LV_ - 1) {            // hi_case from reference
                    ylo = LV_ - 1; yhi = LV_ - 1; ly = 0.0f;
                } else {
                    yhi = ylo + 1; ly = yc - (float)ylo;
                }
                if (ylo == r) w += 1.0f - ly;
                if (yhi == r) w += ly;
            }
        }

        __half  h  = __float2half_rn(w * invc);
        __half2 hh = __half2half2(h);
        w_s[i] = *reinterpret_cast<unsigned*>(&hh);
    }
    __syncthreads();   // weights visible before Phase B

    // ---- Phase B: all 64 threads on same row; lane owns 4 channels.
    //      8-deep LDG batch (MLP=8), HFMA2 chunk-8, promote to f32x2. ----
    __half2  c0 = __float2half2_rn(0.f), c1 = c0;
    uint64_t A0 = 0ull, A1 = 0ull;               // packed f32x2 accumulators

    const uint2* fp = reinterpret_cast<const uint2*>(g_feat16)
                    + (size_t)(bidx[n] * LV_ + rbp) * (D_ / 4) + tid;
    const uint4* wq = reinterpret_cast<const uint4*>(w_s);

    for (int t = nch; t > 0; --t) {
        const uint4 wva = wq[0];                 // rows 0..3 weights
        const uint4 wvb = wq[1];                 // rows 4..7 weights
        wq += 2;
        const uint2 u0 = fp[0 * (D_ / 4)];
        const uint2 u1 = fp[1 * (D_ / 4)];
        const uint2 u2 = fp[2 * (D_ / 4)];
        const uint2 u3 = fp[3 * (D_ / 4)];
        const uint2 u4 = fp[4 * (D_ / 4)];
        const uint2 u5 = fp[5 * (D_ / 4)];
        const uint2 u6 = fp[6 * (D_ / 4)];
        const uint2 u7 = fp[7 * (D_ / 4)];
        fp += 8 * (D_ / 4);

        c0 = __hfma2(u2h(u0.x), u2h(wva.x), c0);
        c1 = __hfma2(u2h(u0.y), u2h(wva.x), c1);
        c0 = __hfma2(u2h(u1.x), u2h(wva.y), c0);
        c1 = __hfma2(u2h(u1.y), u2h(wva.y), c1);
        c0 = __hfma2(u2h(u2.x), u2h(wva.z), c0);
        c1 = __hfma2(u2h(u2.y), u2h(wva.z), c1);
        c0 = __hfma2(u2h(u3.x), u2h(wva.w), c0);
        c1 = __hfma2(u2h(u3.y), u2h(wva.w), c1);
        c0 = __hfma2(u2h(u4.x), u2h(wvb.x), c0);
        c1 = __hfma2(u2h(u4.y), u2h(wvb.x), c1);
        c0 = __hfma2(u2h(u5.x), u2h(wvb.y), c0);
        c1 = __hfma2(u2h(u5.y), u2h(wvb.y), c1);
        c0 = __hfma2(u2h(u6.x), u2h(wvb.z), c0);
        c1 = __hfma2(u2h(u6.y), u2h(wvb.z), c1);
        c0 = __hfma2(u2h(u7.x), u2h(wvb.w), c0);
        c1 = __hfma2(u2h(u7.y), u2h(wvb.w), c1);

        // promote chunk partials to f32x2 accumulators, reset half2 accs
        float2 f0 = __half22float2(c0);
        float2 f1 = __half22float2(c1);
        uint64_t p0, p1;
        asm("mov.b64 %0, {%1, %2};" : "=l"(p0) : "f"(f0.x), "f"(f0.y));
        asm("mov.b64 %0, {%1, %2};" : "=l"(p1) : "f"(f1.x), "f"(f1.y));
        asm("add.rn.f32x2 %0, %0, %1;" : "+l"(A0) : "l"(p0));
        asm("add.rn.f32x2 %0, %0, %1;" : "+l"(A1) : "l"(p1));
        c0 = __float2half2_rn(0.f); c1 = c0;
    }

    // ---- unpack, store (invc already folded into weights) ----
    float o0, o1, o2, o3;
    asm("mov.b64 {%0, %1}, %2;" : "=f"(o0), "=f"(o1) : "l"(A0));
    asm("mov.b64 {%0, %1}, %2;" : "=f"(o2), "=f"(o3) : "l"(A1));

    float4 o = make_float4(o0, o1, o2, o3);
    reinterpret_cast<float4*>(out)[(size_t)blk * (D_ / 4) + tid] = o;
}

extern "C" void kernel_launch(void* const* d_in, const int* in_sizes, int n_in,
                              void* d_out, int out_size)
{
    const float* feat  = (const float*)d_in[0];   // [8, 4096, 256] f32
    const float* boxes = (const float*)d_in[1];   // [2048, 2] f32
    const int*   bidx  = (const int*)  d_in[2];   // [2048] i32
    float*       out   = (float*)d_out;           // [2048, 32, 256] f32

    cvt_kernel<<<(B_ * LV_ * D_ / 8) / 256, 256>>>(feat);
    roi_align1d_kernel<<<N_ * P_, 64>>>(boxes, bidx, out);
}